// round 1
// baseline (speedup 1.0000x reference)
#include <cuda_runtime.h>
#include <math.h>

// Problem constants
#define BB   32     // batch
#define TT   64     // TX == TY
#define DD   512    // embed dim
#define HH   512    // hidden
#define VV   32000  // vocab
#define G4   2048   // 4*H
#define MROW 2048   // T*B rows

// ---------------- scratch (__device__ globals; no allocation allowed) --------
__device__ float g_xz_enc[MROW * G4];   // 16 MB
__device__ float g_xz_dec[MROW * G4];   // 16 MB
__device__ float g_X[MROW * DD];        // 4 MB embedded inputs (reused enc/dec)
__device__ float g_c[BB * HH];          // cell state
__device__ float g_h0[BB * HH];         // h double buffer A
__device__ float g_h1[BB * HH];         // h double buffer B
__device__ float g_hs[BB * TT * HH];    // decoder outputs [b][t][h], 4 MB

__device__ __forceinline__ float sigf(float x) { return 1.0f / (1.0f + expf(-x)); }

// ---------------- zero init --------------------------------------------------
__global__ void zero_kernel(float* p, int n) {
    int i = blockIdx.x * 256 + threadIdx.x;
    if (i < n) p[i] = 0.0f;
}

// ---------------- embedding gather: X[t*B+b][k] = E[ids[b][t]][k] ------------
__global__ void embed_kernel(const int* __restrict__ ids, const float* __restrict__ E,
                             float* __restrict__ X) {
    int r = blockIdx.x;            // r = t*B + b
    int t = r >> 5;                // / 32
    int b = r & 31;
    int tok = ids[b * TT + t];
    const float4* src = (const float4*)(E + (size_t)tok * DD);
    float4* dst = (float4*)(X + (size_t)r * DD);
    dst[threadIdx.x] = src[threadIdx.x];   // 128 threads * float4 = 512 floats
}

// ---------------- fp32 SGEMM: C[M,N] = A[M,K] @ B[K,N] (+bias) ---------------
// BM=128, BN=64, BK=8, 256 threads, 8x4 per thread. M%128==0, N%64==0, K%8==0.
__global__ __launch_bounds__(256)
void sgemm_kernel(const float* __restrict__ A, const float* __restrict__ Bm,
                  const float* __restrict__ bias, float* __restrict__ C,
                  int K, int ldb, int ldc) {
    __shared__ float As[8][128];
    __shared__ float Bs[8][64];
    int tid = threadIdx.x;
    int m0 = blockIdx.y * 128;
    int n0 = blockIdx.x * 64;
    int tx = tid & 15;             // N quad index
    int ty = tid >> 4;             // M oct index
    int arow = tid >> 1, akk = (tid & 1) * 4;
    int bkk  = tid >> 5, bj  = (tid & 31) * 2;

    float acc[8][4];
    #pragma unroll
    for (int i = 0; i < 8; i++)
        #pragma unroll
        for (int j = 0; j < 4; j++) acc[i][j] = 0.0f;

    for (int k0 = 0; k0 < K; k0 += 8) {
        float4 av = *(const float4*)(A + (size_t)(m0 + arow) * K + k0 + akk);
        As[akk + 0][arow] = av.x;
        As[akk + 1][arow] = av.y;
        As[akk + 2][arow] = av.z;
        As[akk + 3][arow] = av.w;
        float2 bv = *(const float2*)(Bm + (size_t)(k0 + bkk) * ldb + n0 + bj);
        Bs[bkk][bj] = bv.x;
        Bs[bkk][bj + 1] = bv.y;
        __syncthreads();
        #pragma unroll
        for (int kk = 0; kk < 8; kk++) {
            float a[8], b[4];
            #pragma unroll
            for (int i = 0; i < 8; i++) a[i] = As[kk][ty * 8 + i];
            #pragma unroll
            for (int j = 0; j < 4; j++) b[j] = Bs[kk][tx * 4 + j];
            #pragma unroll
            for (int i = 0; i < 8; i++)
                #pragma unroll
                for (int j = 0; j < 4; j++) acc[i][j] += a[i] * b[j];
        }
        __syncthreads();
    }
    int n = n0 + tx * 4;
    float4 bv = make_float4(0.f, 0.f, 0.f, 0.f);
    if (bias) bv = *(const float4*)(bias + n);
    #pragma unroll
    for (int i = 0; i < 8; i++) {
        int m = m0 + ty * 8 + i;
        float4 v;
        v.x = acc[i][0] + bv.x;
        v.y = acc[i][1] + bv.y;
        v.z = acc[i][2] + bv.z;
        v.w = acc[i][3] + bv.w;
        *(float4*)(C + (size_t)m * ldc + n) = v;
    }
}

// ---------------- one LSTM timestep ------------------------------------------
// z[b][j] = xz[t*B+b][j] + sum_k h_prev[b][k] * Wh[k][j], then gates + masked
// update. Grid (32 unit-tiles of 16, 4 batch-quarters of 8) = 128 blocks, 256 thr.
// h is double-buffered: GEMM reads h_prev only, writes h_next only (no race).
__global__ __launch_bounds__(256)
void lstm_step_kernel(const float* __restrict__ xz, const float* __restrict__ Wh,
                      const int* __restrict__ len, int t,
                      float* __restrict__ c,
                      const float* __restrict__ h_prev, float* __restrict__ h_next,
                      float* __restrict__ hs) {
    __shared__ float h_s[8][512];
    __shared__ float z_s[64][9];   // padded: conflict-free stores
    int tid = threadIdx.x;
    int u0 = blockIdx.x * 16;      // unit tile base
    int b0 = blockIdx.y * 8;       // batch quarter base

    // cooperative load of h_prev[b0..b0+7][:] (8*512 floats = 1024 float4)
    {
        const float4* src = (const float4*)(h_prev + (size_t)b0 * HH);
        float4* dst = (float4*)(&h_s[0][0]);
        #pragma unroll
        for (int i = 0; i < 4; i++) dst[tid + i * 256] = src[tid + i * 256];
    }
    __syncthreads();

    int j = tid & 63;              // local col: gate g = j>>4, unit uu = j&15
    int brow = tid >> 6;           // 0..3 -> 2 batches each
    int g = j >> 4, uu = j & 15;
    int jg = g * HH + u0 + uu;     // global column in [0, 2048)
    int bb0 = brow * 2;

    float acc0 = xz[(size_t)(t * BB + b0 + bb0) * G4 + jg];
    float acc1 = xz[(size_t)(t * BB + b0 + bb0 + 1) * G4 + jg];
    const float4* h0 = (const float4*)(&h_s[bb0][0]);
    const float4* h1 = (const float4*)(&h_s[bb0 + 1][0]);
    #pragma unroll 2
    for (int k4 = 0; k4 < 128; k4++) {
        int k = k4 * 4;
        float w0 = Wh[(size_t)(k + 0) * G4 + jg];
        float w1 = Wh[(size_t)(k + 1) * G4 + jg];
        float w2 = Wh[(size_t)(k + 2) * G4 + jg];
        float w3 = Wh[(size_t)(k + 3) * G4 + jg];
        float4 ha = h0[k4];
        float4 hb = h1[k4];
        acc0 += w0 * ha.x + w1 * ha.y + w2 * ha.z + w3 * ha.w;
        acc1 += w0 * hb.x + w1 * hb.y + w2 * hb.z + w3 * hb.w;
    }
    z_s[j][bb0] = acc0;
    z_s[j][bb0 + 1] = acc1;
    __syncthreads();

    if (tid < 128) {
        int u = tid & 15;          // local unit
        int bb = tid >> 4;         // local batch 0..7
        float zi = z_s[u][bb];
        float zj = z_s[16 + u][bb];
        float zf = z_s[32 + u][bb];
        float zo = z_s[48 + u][bb];
        int b = b0 + bb;
        int uidx = u0 + u;
        size_t off = (size_t)b * HH + uidx;
        if (t < len[b]) {
            float cn = c[off] * sigf(zf + 1.0f) + sigf(zi) * tanhf(zj);
            float hn = tanhf(cn) * sigf(zo);
            c[off] = cn;
            h_next[off] = hn;
            if (hs) hs[((size_t)b * TT + t) * HH + uidx] = hn;
        } else {
            h_next[off] = h_prev[off];   // frozen state
            if (hs) hs[((size_t)b * TT + t) * HH + uidx] = 0.0f;
        }
    }
}

// ---------------- host launch ------------------------------------------------
extern "C" void kernel_launch(void* const* d_in, const int* in_sizes, int n_in,
                              void* d_out, int out_size) {
    const int*   enc_ids = (const int*)d_in[0];
    const int*   dec_ids = (const int*)d_in[1];
    const int*   len_enc = (const int*)d_in[2];
    const int*   len_dec = (const int*)d_in[3];
    const float* E       = (const float*)d_in[4];
    const float* enc_W   = (const float*)d_in[5];
    const float* enc_b   = (const float*)d_in[6];
    const float* dec_W   = (const float*)d_in[7];
    const float* dec_b   = (const float*)d_in[8];
    const float* proj_W  = (const float*)d_in[9];
    float* out = (float*)d_out;

    float *xz_e, *xz_d, *X, *c, *h0, *h1, *hs;
    cudaGetSymbolAddress((void**)&xz_e, g_xz_enc);
    cudaGetSymbolAddress((void**)&xz_d, g_xz_dec);
    cudaGetSymbolAddress((void**)&X,    g_X);
    cudaGetSymbolAddress((void**)&c,    g_c);
    cudaGetSymbolAddress((void**)&h0,   g_h0);
    cudaGetSymbolAddress((void**)&h1,   g_h1);
    cudaGetSymbolAddress((void**)&hs,   g_hs);
    float* hb[2] = {h0, h1};

    // zero c and both h buffers
    zero_kernel<<<(3 * BB * HH + 255) / 256, 256>>>(c, 3 * BB * HH);  // c,h0,h1 contiguous? not guaranteed
    // (zero each explicitly to be layout-safe)
    zero_kernel<<<(BB * HH + 255) / 256, 256>>>(h0, BB * HH);
    zero_kernel<<<(BB * HH + 255) / 256, 256>>>(h1, BB * HH);
    zero_kernel<<<(BB * HH + 255) / 256, 256>>>(c, BB * HH);

    // ---- encoder ----
    embed_kernel<<<MROW, 128>>>(enc_ids, E, X);
    sgemm_kernel<<<dim3(G4 / 64, MROW / 128), 256>>>(X, enc_W, enc_b, xz_e,
                                                     DD, G4, G4);
    for (int t = 0; t < TT; t++) {
        lstm_step_kernel<<<dim3(32, 4), 256>>>(xz_e, enc_W + (size_t)DD * G4,
                                               len_enc, t, c,
                                               hb[t & 1], hb[(t + 1) & 1], nullptr);
    }
    // after 64 steps, state is in hb[0]

    // ---- decoder ----
    embed_kernel<<<MROW, 128>>>(dec_ids, E, X);
    sgemm_kernel<<<dim3(G4 / 64, MROW / 128), 256>>>(X, dec_W, dec_b, xz_d,
                                                     DD, G4, G4);
    for (int t = 0; t < TT; t++) {
        lstm_step_kernel<<<dim3(32, 4), 256>>>(xz_d, dec_W + (size_t)DD * G4,
                                               len_dec, t, c,
                                               hb[t & 1], hb[(t + 1) & 1], hs);
    }

    // ---- vocab projection: out[b][t][v] = hs[b][t][:] @ proj_W ----
    sgemm_kernel<<<dim3(VV / 64, MROW / 128), 256>>>(hs, proj_W, nullptr, out,
                                                     HH, VV, VV);
}

// round 4
// speedup vs baseline: 1.3650x; 1.3650x over previous
#include <cuda_runtime.h>
#include <math.h>
#include <stdint.h>

// Problem constants
#define BB   32
#define TT   64
#define DD   512
#define HH   512
#define VV   32000
#define G4   2048
#define MROW 2048    // T*B

// GEMM tiling
#define BM 128
#define BN 128
#define BK 32
#define NCHUNK (DD / BK)              // 16
#define TILE_B (128 * 128)            // 16KB per operand tile
#define GEMM_SMEM (1024 + 4 * TILE_B) // align pad + 2 bufs * (A+B)

// ---------------- scratch (__device__ globals) -------------------------------
__device__ float g_xz_enc[MROW * G4];
__device__ float g_xz_dec[MROW * G4];
__device__ float g_X[MROW * DD];
__device__ float g_c[BB * HH];
__device__ float g_h0[BB * HH];
__device__ float g_h1[BB * HH];
__device__ float g_hs[BB * TT * HH];
__device__ float g_WtP[(size_t)VV * DD];   // proj_W^T  [32000,512] (tf32-rounded)
__device__ float g_WtE[(size_t)G4 * DD];   // enc_W x-part^T [2048,512]
__device__ float g_WtD[(size_t)G4 * DD];   // dec_W x-part^T [2048,512]

__device__ __forceinline__ float sigf(float x) { return 1.0f / (1.0f + expf(-x)); }

__device__ __forceinline__ float f2tf(float x) {
    uint32_t r;
    asm("cvt.rna.tf32.f32 %0, %1;" : "=r"(r) : "f"(x));
    return __uint_as_float(r);
}

__device__ __forceinline__ uint32_t s2u(const void* p) {
    uint32_t a;
    asm("{ .reg .u64 t; cvta.to.shared.u64 t, %1; cvt.u32.u64 %0, t; }" : "=r"(a) : "l"(p));
    return a;
}

#define CP_ASYNC16(sdst, gsrc) \
    asm volatile("cp.async.cg.shared.global [%0], [%1], 16;" :: "r"(sdst), "l"(gsrc))
#define CP_COMMIT() asm volatile("cp.async.commit_group;" ::: "memory")
#define CP_WAIT1()  asm volatile("cp.async.wait_group 1;" ::: "memory")
#define CP_WAIT0()  asm volatile("cp.async.wait_group 0;" ::: "memory")

#define LDSM_X4(r0, r1, r2, r3, addr) \
    asm volatile("ldmatrix.sync.aligned.m8n8.x4.shared.b16 {%0,%1,%2,%3}, [%4];" \
        : "=r"(r0), "=r"(r1), "=r"(r2), "=r"(r3) : "r"(addr))

#define MMA_TF32(c, a, b0, b1) \
    asm volatile("mma.sync.aligned.m16n8k8.row.col.f32.tf32.tf32.f32 " \
        "{%0,%1,%2,%3}, {%4,%5,%6,%7}, {%8,%9}, {%0,%1,%2,%3};" \
        : "+f"((c)[0]), "+f"((c)[1]), "+f"((c)[2]), "+f"((c)[3]) \
        : "r"((a)[0]), "r"((a)[1]), "r"((a)[2]), "r"((a)[3]), "r"(b0), "r"(b1))

// ---------------- small kernels ---------------------------------------------
__global__ void zero_kernel(float* p, int n) {
    int i = blockIdx.x * 256 + threadIdx.x;
    if (i < n) p[i] = 0.0f;
}

// dst[c][r] = tf32(src[r][c]); src is [R, C] row-major
__global__ void transpose_kernel(const float* __restrict__ src, float* __restrict__ dst,
                                 int R, int C) {
    __shared__ float tile[32][33];
    int c0 = blockIdx.x * 32, r0 = blockIdx.y * 32;
    int tx = threadIdx.x, ty = threadIdx.y;  // (32, 8)
    #pragma unroll
    for (int i = 0; i < 32; i += 8)
        tile[ty + i][tx] = src[(size_t)(r0 + ty + i) * C + c0 + tx];
    __syncthreads();
    #pragma unroll
    for (int i = 0; i < 32; i += 8)
        dst[(size_t)(c0 + ty + i) * R + r0 + tx] = f2tf(tile[tx][ty + i]);
}

// X[t*B+b][k] = tf32(E[ids[b][t]][k])
__global__ void embed_kernel(const int* __restrict__ ids, const float* __restrict__ E,
                             float* __restrict__ X) {
    int r = blockIdx.x;
    int t = r >> 5;
    int b = r & 31;
    int tok = ids[b * TT + t];
    const float4* src = (const float4*)(E + (size_t)tok * DD);
    float4 v = src[threadIdx.x];
    v.x = f2tf(v.x); v.y = f2tf(v.y); v.z = f2tf(v.z); v.w = f2tf(v.w);
    ((float4*)(X + (size_t)r * DD))[threadIdx.x] = v;
}

// ---------------- tf32 mma.sync GEMM -----------------------------------------
// C[M, N] = A[M, 512] @ Bt[N, 512]^T (+bias). Operands pre-rounded to tf32.
// Tiles SW128-swizzled: row r (128B), seg16 s: off = r*128 + s*16, sw ^= (r&7)<<4.
__device__ __forceinline__ void ld_tile(const float* __restrict__ src, size_t row0,
                                        int kc, uint32_t sbase, int tid) {
    #pragma unroll
    for (int i = 0; i < 4; i++) {
        int s = tid + i * 256;          // 0..1023
        int r = s >> 3, cs = s & 7;
        const float* g = src + (row0 + r) * DD + kc * BK + cs * 4;
        uint32_t off = (uint32_t)(r * 128 + cs * 16) ^ ((r & 7) << 4);
        CP_ASYNC16(sbase + off, g);
    }
}

__global__ __launch_bounds__(256)
void tf32_gemm_kernel(const float* __restrict__ A, const float* __restrict__ Bt,
                      const float* __restrict__ bias, float* __restrict__ C, int ldc) {
    extern __shared__ char smem_raw[];
    uint32_t raw_u = s2u(smem_raw);
    uint32_t base_u = (raw_u + 1023) & ~1023u;
    uint32_t sa_u[2] = { base_u,              base_u + 2 * TILE_B };
    uint32_t sb_u[2] = { base_u + TILE_B,     base_u + 3 * TILE_B };

    int tid = threadIdx.x;
    int lane = tid & 31, wid = tid >> 5;
    int wm = wid & 3, wn = wid >> 2;       // warp grid 4(m) x 2(n)
    size_t m0 = (size_t)blockIdx.y * BM;
    size_t n0 = (size_t)blockIdx.x * BN;

    // ldmatrix per-thread addressing
    int q = lane >> 3;
    int ar = wm * 32 + (q & 1) * 8 + (lane & 7);          // A row (+ mt*16)
    uint32_t apre[2], amask = (uint32_t)((ar & 7) << 4);
    apre[0] = (uint32_t)(ar * 128 + (q >> 1) * 16);
    apre[1] = apre[0] + 16 * 128;
    int br = wn * 64 + (q >> 1) * 8 + (lane & 7);         // B row (+ np*16)
    uint32_t bpre[4], bmask = (uint32_t)((br & 7) << 4);
    bpre[0] = (uint32_t)(br * 128 + (q & 1) * 16);
    bpre[1] = bpre[0] + 16 * 128;
    bpre[2] = bpre[0] + 32 * 128;
    bpre[3] = bpre[0] + 48 * 128;

    float acc[2][8][4];
    #pragma unroll
    for (int i = 0; i < 2; i++)
        #pragma unroll
        for (int j = 0; j < 8; j++)
            #pragma unroll
            for (int k = 0; k < 4; k++) acc[i][j][k] = 0.0f;

    // prologue: load chunk 0 into buf 0
    ld_tile(A,  m0, 0, sa_u[0], tid);
    ld_tile(Bt, n0, 0, sb_u[0], tid);
    CP_COMMIT();

    int buf = 0;
    #pragma unroll 1
    for (int it = 0; it < NCHUNK; it++) {
        if (it + 1 < NCHUNK) {
            ld_tile(A,  m0, it + 1, sa_u[buf ^ 1], tid);
            ld_tile(Bt, n0, it + 1, sb_u[buf ^ 1], tid);
            CP_COMMIT();
            CP_WAIT1();
        } else {
            CP_WAIT0();
        }
        __syncthreads();

        uint32_t As = sa_u[buf], Bs = sb_u[buf];
        #pragma unroll
        for (int ks = 0; ks < 4; ks++) {
            uint32_t a[2][4], b[4][4];
            #pragma unroll
            for (int mt = 0; mt < 2; mt++)
                LDSM_X4(a[mt][0], a[mt][1], a[mt][2], a[mt][3],
                        As + (((apre[mt] + ks * 32) ^ amask)));
            #pragma unroll
            for (int np = 0; np < 4; np++)
                LDSM_X4(b[np][0], b[np][1], b[np][2], b[np][3],
                        Bs + (((bpre[np] + ks * 32) ^ bmask)));
            #pragma unroll
            for (int mt = 0; mt < 2; mt++)
                #pragma unroll
                for (int nt = 0; nt < 8; nt++)
                    MMA_TF32(acc[mt][nt], a[mt], b[nt >> 1][(nt & 1) * 2],
                             b[nt >> 1][(nt & 1) * 2 + 1]);
        }
        __syncthreads();
        buf ^= 1;
    }

    // epilogue
    int g = lane >> 2, tg = lane & 3;
    #pragma unroll
    for (int mt = 0; mt < 2; mt++) {
        size_t row = m0 + wm * 32 + mt * 16 + g;
        #pragma unroll
        for (int nt = 0; nt < 8; nt++) {
            size_t col = n0 + wn * 64 + nt * 8 + 2 * tg;
            float b0 = 0.f, b1 = 0.f;
            if (bias) { b0 = bias[col]; b1 = bias[col + 1]; }
            float2 v0 = make_float2(acc[mt][nt][0] + b0, acc[mt][nt][1] + b1);
            float2 v1 = make_float2(acc[mt][nt][2] + b0, acc[mt][nt][3] + b1);
            *(float2*)(C + row * (size_t)ldc + col)       = v0;
            *(float2*)(C + (row + 8) * (size_t)ldc + col) = v1;
        }
    }
}

// ---------------- one LSTM timestep ------------------------------------------
__global__ __launch_bounds__(256)
void lstm_step_kernel(const float* __restrict__ xz, const float* __restrict__ Wh,
                      const int* __restrict__ len, int t,
                      float* __restrict__ c,
                      const float* __restrict__ h_prev, float* __restrict__ h_next,
                      float* __restrict__ hs) {
    __shared__ float h_s[8][512];
    __shared__ float z_s[64][9];
    int tid = threadIdx.x;
    int u0 = blockIdx.x * 16;
    int b0 = blockIdx.y * 8;

    {
        const float4* src = (const float4*)(h_prev + (size_t)b0 * HH);
        float4* dst = (float4*)(&h_s[0][0]);
        #pragma unroll
        for (int i = 0; i < 4; i++) dst[tid + i * 256] = src[tid + i * 256];
    }
    __syncthreads();

    int j = tid & 63;
    int brow = tid >> 6;
    int g = j >> 4, uu = j & 15;
    int jg = g * HH + u0 + uu;
    int bb0 = brow * 2;

    float acc0 = xz[(size_t)(t * BB + b0 + bb0) * G4 + jg];
    float acc1 = xz[(size_t)(t * BB + b0 + bb0 + 1) * G4 + jg];
    const float4* h0 = (const float4*)(&h_s[bb0][0]);
    const float4* h1 = (const float4*)(&h_s[bb0 + 1][0]);
    #pragma unroll 2
    for (int k4 = 0; k4 < 128; k4++) {
        int k = k4 * 4;
        float w0 = Wh[(size_t)(k + 0) * G4 + jg];
        float w1 = Wh[(size_t)(k + 1) * G4 + jg];
        float w2 = Wh[(size_t)(k + 2) * G4 + jg];
        float w3 = Wh[(size_t)(k + 3) * G4 + jg];
        float4 ha = h0[k4];
        float4 hb = h1[k4];
        acc0 += w0 * ha.x + w1 * ha.y + w2 * ha.z + w3 * ha.w;
        acc1 += w0 * hb.x + w1 * hb.y + w2 * hb.z + w3 * hb.w;
    }
    z_s[j][bb0] = acc0;
    z_s[j][bb0 + 1] = acc1;
    __syncthreads();

    if (tid < 128) {
        int u = tid & 15;
        int bb = tid >> 4;
        float zi = z_s[u][bb];
        float zj = z_s[16 + u][bb];
        float zf = z_s[32 + u][bb];
        float zo = z_s[48 + u][bb];
        int b = b0 + bb;
        int uidx = u0 + u;
        size_t off = (size_t)b * HH + uidx;
        if (t < len[b]) {
            float cn = c[off] * sigf(zf + 1.0f) + sigf(zi) * tanhf(zj);
            float hn = tanhf(cn) * sigf(zo);
            c[off] = cn;
            h_next[off] = hn;
            if (hs) hs[((size_t)b * TT + t) * HH + uidx] = f2tf(hn);
        } else {
            h_next[off] = h_prev[off];
            if (hs) hs[((size_t)b * TT + t) * HH + uidx] = 0.0f;
        }
    }
}

// ---------------- host launch ------------------------------------------------
extern "C" void kernel_launch(void* const* d_in, const int* in_sizes, int n_in,
                              void* d_out, int out_size) {
    const int*   enc_ids = (const int*)d_in[0];
    const int*   dec_ids = (const int*)d_in[1];
    const int*   len_enc = (const int*)d_in[2];
    const int*   len_dec = (const int*)d_in[3];
    const float* E       = (const float*)d_in[4];
    const float* enc_W   = (const float*)d_in[5];
    const float* enc_b   = (const float*)d_in[6];
    const float* dec_W   = (const float*)d_in[7];
    const float* dec_b   = (const float*)d_in[8];
    const float* proj_W  = (const float*)d_in[9];
    float* out = (float*)d_out;

    float *xz_e, *xz_d, *X, *c, *h0, *h1, *hs, *WtP, *WtE, *WtD;
    cudaGetSymbolAddress((void**)&xz_e, g_xz_enc);
    cudaGetSymbolAddress((void**)&xz_d, g_xz_dec);
    cudaGetSymbolAddress((void**)&X,    g_X);
    cudaGetSymbolAddress((void**)&c,    g_c);
    cudaGetSymbolAddress((void**)&h0,   g_h0);
    cudaGetSymbolAddress((void**)&h1,   g_h1);
    cudaGetSymbolAddress((void**)&hs,   g_hs);
    cudaGetSymbolAddress((void**)&WtP,  g_WtP);
    cudaGetSymbolAddress((void**)&WtE,  g_WtE);
    cudaGetSymbolAddress((void**)&WtD,  g_WtD);
    float* hb[2] = {h0, h1};

    cudaFuncSetAttribute(tf32_gemm_kernel,
                         cudaFuncAttributeMaxDynamicSharedMemorySize, GEMM_SMEM);

    // weight transposes + tf32 rounding: [512, N] -> [N, 512]
    transpose_kernel<<<dim3(VV / 32, DD / 32), dim3(32, 8)>>>(proj_W, WtP, DD, VV);
    transpose_kernel<<<dim3(G4 / 32, DD / 32), dim3(32, 8)>>>(enc_W, WtE, DD, G4);
    transpose_kernel<<<dim3(G4 / 32, DD / 32), dim3(32, 8)>>>(dec_W, WtD, DD, G4);

    zero_kernel<<<(BB * HH + 255) / 256, 256>>>(h0, BB * HH);
    zero_kernel<<<(BB * HH + 255) / 256, 256>>>(h1, BB * HH);
    zero_kernel<<<(BB * HH + 255) / 256, 256>>>(c, BB * HH);

    // ---- encoder ----
    embed_kernel<<<MROW, 128>>>(enc_ids, E, X);
    tf32_gemm_kernel<<<dim3(G4 / BN, MROW / BM), 256, GEMM_SMEM>>>(X, WtE, enc_b, xz_e, G4);
    for (int t = 0; t < TT; t++) {
        lstm_step_kernel<<<dim3(32, 4), 256>>>(xz_e, enc_W + (size_t)DD * G4,
                                               len_enc, t, c,
                                               hb[t & 1], hb[(t + 1) & 1], nullptr);
    }

    // ---- decoder ----
    embed_kernel<<<MROW, 128>>>(dec_ids, E, X);
    tf32_gemm_kernel<<<dim3(G4 / BN, MROW / BM), 256, GEMM_SMEM>>>(X, WtD, dec_b, xz_d, G4);
    for (int t = 0; t < TT; t++) {
        lstm_step_kernel<<<dim3(32, 4), 256>>>(xz_d, dec_W + (size_t)DD * G4,
                                               len_dec, t, c,
                                               hb[t & 1], hb[(t + 1) & 1], hs);
    }

    // ---- vocab projection ----
    tf32_gemm_kernel<<<dim3(VV / BN, MROW / BM), 256, GEMM_SMEM>>>(hs, WtP, nullptr, out, VV);
}

// round 5
// speedup vs baseline: 3.7797x; 2.7691x over previous
#include <cuda_runtime.h>
#include <math.h>
#include <stdint.h>

// Problem constants
#define BB   32
#define TT   64
#define DD   512
#define HH   512
#define VV   32000
#define G4   2048
#define MROW 2048    // T*B

// GEMM tiling
#define BM 128
#define BN 128
#define BK 32
#define NCHUNK (DD / BK)              // 16
#define TILE_B (128 * 128)            // 16KB per operand tile
#define GEMM_SMEM (1024 + 4 * TILE_B)

// Persistent LSTM
#define NBLK 128
#define WH_STRIDE 516                 // 512 + 4 pad floats (odd multiple of 4)
#define LSTM_SMEM (64 * WH_STRIDE * 4)  // 132096 bytes

// ---------------- scratch (__device__ globals) -------------------------------
__device__ float g_xz_enc[MROW * G4];
__device__ float g_xz_dec[MROW * G4];
__device__ float g_X[MROW * DD];
__device__ float g_state[3 * BB * HH + 16];  // c | h0 | h1 | barrier counters
__device__ float g_hs[BB * TT * HH];
__device__ float g_WtP[(size_t)VV * DD];
__device__ float g_WtE[(size_t)G4 * DD];
__device__ float g_WtD[(size_t)G4 * DD];

__device__ __forceinline__ float sigf(float x) { return 1.0f / (1.0f + expf(-x)); }

__device__ __forceinline__ float f2tf(float x) {
    uint32_t r;
    asm("cvt.rna.tf32.f32 %0, %1;" : "=r"(r) : "f"(x));
    return __uint_as_float(r);
}

__device__ __forceinline__ uint32_t s2u(const void* p) {
    uint32_t a;
    asm("{ .reg .u64 t; cvta.to.shared.u64 t, %1; cvt.u32.u64 %0, t; }" : "=r"(a) : "l"(p));
    return a;
}

#define CP_ASYNC16(sdst, gsrc) \
    asm volatile("cp.async.cg.shared.global [%0], [%1], 16;" :: "r"(sdst), "l"(gsrc))
#define CP_COMMIT() asm volatile("cp.async.commit_group;" ::: "memory")
#define CP_WAIT1()  asm volatile("cp.async.wait_group 1;" ::: "memory")
#define CP_WAIT0()  asm volatile("cp.async.wait_group 0;" ::: "memory")

#define LDSM_X4(r0, r1, r2, r3, addr) \
    asm volatile("ldmatrix.sync.aligned.m8n8.x4.shared.b16 {%0,%1,%2,%3}, [%4];" \
        : "=r"(r0), "=r"(r1), "=r"(r2), "=r"(r3) : "r"(addr))

#define MMA_TF32(c, a, b0, b1) \
    asm volatile("mma.sync.aligned.m16n8k8.row.col.f32.tf32.tf32.f32 " \
        "{%0,%1,%2,%3}, {%4,%5,%6,%7}, {%8,%9}, {%0,%1,%2,%3};" \
        : "+f"((c)[0]), "+f"((c)[1]), "+f"((c)[2]), "+f"((c)[3]) \
        : "r"((a)[0]), "r"((a)[1]), "r"((a)[2]), "r"((a)[3]), "r"(b0), "r"(b1))

// ---------------- small kernels ---------------------------------------------
__global__ void zero_kernel(float* p, int n) {
    int i = blockIdx.x * 256 + threadIdx.x;
    if (i < n) p[i] = 0.0f;
}

// dst[c][r] = tf32(src[r][c]); src is [R, C] row-major
__global__ void transpose_kernel(const float* __restrict__ src, float* __restrict__ dst,
                                 int R, int C) {
    __shared__ float tile[32][33];
    int c0 = blockIdx.x * 32, r0 = blockIdx.y * 32;
    int tx = threadIdx.x, ty = threadIdx.y;  // (32, 8)
    #pragma unroll
    for (int i = 0; i < 32; i += 8)
        tile[ty + i][tx] = src[(size_t)(r0 + ty + i) * C + c0 + tx];
    __syncthreads();
    #pragma unroll
    for (int i = 0; i < 32; i += 8)
        dst[(size_t)(c0 + ty + i) * R + r0 + tx] = f2tf(tile[tx][ty + i]);
}

__global__ void embed_kernel(const int* __restrict__ ids, const float* __restrict__ E,
                             float* __restrict__ X) {
    int r = blockIdx.x;
    int t = r >> 5;
    int b = r & 31;
    int tok = ids[b * TT + t];
    const float4* src = (const float4*)(E + (size_t)tok * DD);
    float4 v = src[threadIdx.x];
    v.x = f2tf(v.x); v.y = f2tf(v.y); v.z = f2tf(v.z); v.w = f2tf(v.w);
    ((float4*)(X + (size_t)r * DD))[threadIdx.x] = v;
}

// ---------------- tf32 mma.sync GEMM (unchanged from R4, validated) ----------
__device__ __forceinline__ void ld_tile(const float* __restrict__ src, size_t row0,
                                        int kc, uint32_t sbase, int tid) {
    #pragma unroll
    for (int i = 0; i < 4; i++) {
        int s = tid + i * 256;
        int r = s >> 3, cs = s & 7;
        const float* g = src + (row0 + r) * DD + kc * BK + cs * 4;
        uint32_t off = (uint32_t)(r * 128 + cs * 16) ^ ((r & 7) << 4);
        CP_ASYNC16(sbase + off, g);
    }
}

__global__ __launch_bounds__(256)
void tf32_gemm_kernel(const float* __restrict__ A, const float* __restrict__ Bt,
                      const float* __restrict__ bias, float* __restrict__ C, int ldc) {
    extern __shared__ char smem_raw[];
    uint32_t raw_u = s2u(smem_raw);
    uint32_t base_u = (raw_u + 1023) & ~1023u;
    uint32_t sa_u[2] = { base_u,          base_u + 2 * TILE_B };
    uint32_t sb_u[2] = { base_u + TILE_B, base_u + 3 * TILE_B };

    int tid = threadIdx.x;
    int lane = tid & 31, wid = tid >> 5;
    int wm = wid & 3, wn = wid >> 2;
    size_t m0 = (size_t)blockIdx.y * BM;
    size_t n0 = (size_t)blockIdx.x * BN;

    int q = lane >> 3;
    int ar = wm * 32 + (q & 1) * 8 + (lane & 7);
    uint32_t apre[2], amask = (uint32_t)((ar & 7) << 4);
    apre[0] = (uint32_t)(ar * 128 + (q >> 1) * 16);
    apre[1] = apre[0] + 16 * 128;
    int br = wn * 64 + (q >> 1) * 8 + (lane & 7);
    uint32_t bpre[4], bmask = (uint32_t)((br & 7) << 4);
    bpre[0] = (uint32_t)(br * 128 + (q & 1) * 16);
    bpre[1] = bpre[0] + 16 * 128;
    bpre[2] = bpre[0] + 32 * 128;
    bpre[3] = bpre[0] + 48 * 128;

    float acc[2][8][4];
    #pragma unroll
    for (int i = 0; i < 2; i++)
        #pragma unroll
        for (int j = 0; j < 8; j++)
            #pragma unroll
            for (int k = 0; k < 4; k++) acc[i][j][k] = 0.0f;

    ld_tile(A,  m0, 0, sa_u[0], tid);
    ld_tile(Bt, n0, 0, sb_u[0], tid);
    CP_COMMIT();

    int buf = 0;
    #pragma unroll 1
    for (int it = 0; it < NCHUNK; it++) {
        if (it + 1 < NCHUNK) {
            ld_tile(A,  m0, it + 1, sa_u[buf ^ 1], tid);
            ld_tile(Bt, n0, it + 1, sb_u[buf ^ 1], tid);
            CP_COMMIT();
            CP_WAIT1();
        } else {
            CP_WAIT0();
        }
        __syncthreads();

        uint32_t As = sa_u[buf], Bs = sb_u[buf];
        #pragma unroll
        for (int ks = 0; ks < 4; ks++) {
            uint32_t a[2][4], b[4][4];
            #pragma unroll
            for (int mt = 0; mt < 2; mt++)
                LDSM_X4(a[mt][0], a[mt][1], a[mt][2], a[mt][3],
                        As + (((apre[mt] + ks * 32) ^ amask)));
            #pragma unroll
            for (int np = 0; np < 4; np++)
                LDSM_X4(b[np][0], b[np][1], b[np][2], b[np][3],
                        Bs + (((bpre[np] + ks * 32) ^ bmask)));
            #pragma unroll
            for (int mt = 0; mt < 2; mt++)
                #pragma unroll
                for (int nt = 0; nt < 8; nt++)
                    MMA_TF32(acc[mt][nt], a[mt], b[nt >> 1][(nt & 1) * 2],
                             b[nt >> 1][(nt & 1) * 2 + 1]);
        }
        __syncthreads();
        buf ^= 1;
    }

    int g = lane >> 2, tg = lane & 3;
    #pragma unroll
    for (int mt = 0; mt < 2; mt++) {
        size_t row = m0 + wm * 32 + mt * 16 + g;
        #pragma unroll
        for (int nt = 0; nt < 8; nt++) {
            size_t col = n0 + wn * 64 + nt * 8 + 2 * tg;
            float b0 = 0.f, b1 = 0.f;
            if (bias) { b0 = bias[col]; b1 = bias[col + 1]; }
            float2 v0 = make_float2(acc[mt][nt][0] + b0, acc[mt][nt][1] + b1);
            float2 v1 = make_float2(acc[mt][nt][2] + b0, acc[mt][nt][3] + b1);
            *(float2*)(C + row * (size_t)ldc + col)       = v0;
            *(float2*)(C + (row + 8) * (size_t)ldc + col) = v1;
        }
    }
}

// ---------------- persistent LSTM (64 steps, one kernel) ---------------------
// 128 blocks (1/SM, all resident). Wh cached in SMEM. Grid barrier per step.
__global__ __launch_bounds__(256)
void lstm_persistent_kernel(const float* __restrict__ xz, const float* __restrict__ Wh,
                            const int* __restrict__ len, float* __restrict__ c,
                            float* __restrict__ hbuf0, float* __restrict__ hbuf1,
                            float* __restrict__ hs, unsigned* __restrict__ bar) {
    extern __shared__ float WhS[];       // [64][WH_STRIDE]
    __shared__ float h_s[8][512];
    __shared__ float z_s[64][9];
    int tid = threadIdx.x;
    int ux = blockIdx.x & 31, bq = blockIdx.x >> 5;
    int u0 = ux * 16, b0 = bq * 8;

    // preload this block's 64 Wh columns (jl -> global col jg)
    for (int i = tid; i < 64 * 512; i += 256) {
        int jl = i & 63, k = i >> 6;
        int jg = ((jl >> 4) << 9) + u0 + (jl & 15);
        WhS[jl * WH_STRIDE + k] = Wh[(size_t)k * G4 + jg];
    }

    int jl = tid & 63;
    int bb0 = (tid >> 6) * 2;
    int jg = ((jl >> 4) << 9) + u0 + (jl & 15);
    const float4* w4 = (const float4*)(WhS + jl * WH_STRIDE);
    int u = tid & 15, bb = (tid >> 4) & 7;   // gate-phase mapping (tid < 128)
    __syncthreads();

    float* hb[2] = { hbuf0, hbuf1 };
    for (int t = 0; t < TT; t++) {
        const float* h_prev = hb[t & 1];
        float* h_next = hb[(t + 1) & 1];
        {
            const float4* src = (const float4*)(h_prev + (size_t)b0 * HH);
            float4* dst = (float4*)(&h_s[0][0]);
            #pragma unroll
            for (int i = 0; i < 4; i++) dst[tid + i * 256] = src[tid + i * 256];
        }
        __syncthreads();

        float acc0 = xz[(size_t)(t * BB + b0 + bb0) * G4 + jg];
        float acc1 = xz[(size_t)(t * BB + b0 + bb0 + 1) * G4 + jg];
        const float4* h4a = (const float4*)(&h_s[bb0][0]);
        const float4* h4b = (const float4*)(&h_s[bb0 + 1][0]);
        #pragma unroll 4
        for (int k4 = 0; k4 < 128; k4++) {
            float4 w = w4[k4];
            float4 x = h4a[k4], y = h4b[k4];
            acc0 += w.x * x.x + w.y * x.y + w.z * x.z + w.w * x.w;
            acc1 += w.x * y.x + w.y * y.y + w.z * y.z + w.w * y.w;
        }
        z_s[jl][bb0] = acc0;
        z_s[jl][bb0 + 1] = acc1;
        __syncthreads();

        if (tid < 128) {
            float zi = z_s[u][bb];
            float zj = z_s[16 + u][bb];
            float zf = z_s[32 + u][bb];
            float zo = z_s[48 + u][bb];
            int b = b0 + bb;
            int uidx = u0 + u;
            size_t off = (size_t)b * HH + uidx;
            if (t < len[b]) {
                float cn = c[off] * sigf(zf + 1.0f) + sigf(zi) * tanhf(zj);
                float hn = tanhf(cn) * sigf(zo);
                c[off] = cn;
                h_next[off] = hn;
                if (hs) hs[((size_t)b * TT + t) * HH + uidx] = f2tf(hn);
            } else {
                h_next[off] = h_prev[off];
                if (hs) hs[((size_t)b * TT + t) * HH + uidx] = 0.0f;
            }
        }
        __syncthreads();
        // grid barrier (all 128 blocks resident)
        if (tid == 0) {
            __threadfence();
            atomicAdd(bar, 1u);
            unsigned target = (unsigned)NBLK * (t + 1);
            unsigned v;
            do {
                asm volatile("ld.acquire.gpu.u32 %0, [%1];" : "=r"(v) : "l"(bar));
            } while (v < target);
        }
        __syncthreads();
    }
}

// ---------------- host launch ------------------------------------------------
extern "C" void kernel_launch(void* const* d_in, const int* in_sizes, int n_in,
                              void* d_out, int out_size) {
    const int*   enc_ids = (const int*)d_in[0];
    const int*   dec_ids = (const int*)d_in[1];
    const int*   len_enc = (const int*)d_in[2];
    const int*   len_dec = (const int*)d_in[3];
    const float* E       = (const float*)d_in[4];
    const float* enc_W   = (const float*)d_in[5];
    const float* enc_b   = (const float*)d_in[6];
    const float* dec_W   = (const float*)d_in[7];
    const float* dec_b   = (const float*)d_in[8];
    const float* proj_W  = (const float*)d_in[9];
    float* out = (float*)d_out;

    float *xz_e, *xz_d, *X, *state, *hs, *WtP, *WtE, *WtD;
    cudaGetSymbolAddress((void**)&xz_e,  g_xz_enc);
    cudaGetSymbolAddress((void**)&xz_d,  g_xz_dec);
    cudaGetSymbolAddress((void**)&X,     g_X);
    cudaGetSymbolAddress((void**)&state, g_state);
    cudaGetSymbolAddress((void**)&hs,    g_hs);
    cudaGetSymbolAddress((void**)&WtP,   g_WtP);
    cudaGetSymbolAddress((void**)&WtE,   g_WtE);
    cudaGetSymbolAddress((void**)&WtD,   g_WtD);
    float* c  = state;
    float* h0 = state + BB * HH;
    float* h1 = state + 2 * BB * HH;
    unsigned* bars = (unsigned*)(state + 3 * BB * HH);

    cudaFuncSetAttribute(tf32_gemm_kernel,
                         cudaFuncAttributeMaxDynamicSharedMemorySize, GEMM_SMEM);
    cudaFuncSetAttribute(lstm_persistent_kernel,
                         cudaFuncAttributeMaxDynamicSharedMemorySize, LSTM_SMEM);

    // [0] zero all state (c, h0, h1, barrier counters)
    zero_kernel<<<(3 * BB * HH + 16 + 255) / 256, 256>>>(state, 3 * BB * HH + 16);
    // [1..3] weight transposes + tf32 rounding
    transpose_kernel<<<dim3(VV / 32, DD / 32), dim3(32, 8)>>>(proj_W, WtP, DD, VV);
    transpose_kernel<<<dim3(G4 / 32, DD / 32), dim3(32, 8)>>>(enc_W, WtE, DD, G4);
    transpose_kernel<<<dim3(G4 / 32, DD / 32), dim3(32, 8)>>>(dec_W, WtD, DD, G4);

    // ---- encoder ----
    // [4] embed, [5] input GEMM (profiled by ncu -s 5 -c 1), [6] persistent LSTM
    embed_kernel<<<MROW, 128>>>(enc_ids, E, X);
    tf32_gemm_kernel<<<dim3(G4 / BN, MROW / BM), 256, GEMM_SMEM>>>(X, WtE, enc_b, xz_e, G4);
    lstm_persistent_kernel<<<NBLK, 256, LSTM_SMEM>>>(xz_e, enc_W + (size_t)DD * G4,
                                                     len_enc, c, h0, h1, nullptr, bars);

    // ---- decoder ----
    embed_kernel<<<MROW, 128>>>(dec_ids, E, X);
    tf32_gemm_kernel<<<dim3(G4 / BN, MROW / BM), 256, GEMM_SMEM>>>(X, WtD, dec_b, xz_d, G4);
    lstm_persistent_kernel<<<NBLK, 256, LSTM_SMEM>>>(xz_d, dec_W + (size_t)DD * G4,
                                                     len_dec, c, h0, h1, hs, bars + 1);

    // ---- vocab projection ----
    tf32_gemm_kernel<<<dim3(VV / BN, MROW / BM), 256, GEMM_SMEM>>>(hs, WtP, nullptr, out, VV);
}

// round 6
// speedup vs baseline: 3.7910x; 1.0030x over previous
#include <cuda_runtime.h>
#include <math.h>
#include <stdint.h>

// Problem constants
#define BB   32
#define TT   64
#define DD   512
#define HH   512
#define VV   32000
#define G4   2048
#define MROW 2048    // T*B

// GEMM tiling
#define BM 128
#define BN 128
#define BK 32
#define NCHUNK (DD / BK)              // 16
#define TILE_B (128 * 128)            // 16KB per operand tile
#define GEMM_SMEM (1024 + 4 * TILE_B)

#define NBLK 128

// ---------------- scratch (__device__ globals) -------------------------------
__device__ float g_xz_enc[MROW * G4];
__device__ float g_xz_dec[MROW * G4];
__device__ float g_X[MROW * DD];
// state: c [32*512] | hp0 packed [16*512*2] | hp1 packed [16*512*2] | bars[16]
__device__ float g_state[3 * BB * HH + 16];
__device__ float g_hs[BB * TT * HH];
__device__ float g_WtP[(size_t)VV * DD];
__device__ float g_WtE[(size_t)G4 * DD];
__device__ float g_WtD[(size_t)G4 * DD];

__device__ __forceinline__ float sigf(float x) { return 1.0f / (1.0f + expf(-x)); }

__device__ __forceinline__ float f2tf(float x) {
    uint32_t r;
    asm("cvt.rna.tf32.f32 %0, %1;" : "=r"(r) : "f"(x));
    return __uint_as_float(r);
}

__device__ __forceinline__ uint32_t s2u(const void* p) {
    uint32_t a;
    asm("{ .reg .u64 t; cvta.to.shared.u64 t, %1; cvt.u32.u64 %0, t; }" : "=r"(a) : "l"(p));
    return a;
}

#define CP_ASYNC16(sdst, gsrc) \
    asm volatile("cp.async.cg.shared.global [%0], [%1], 16;" :: "r"(sdst), "l"(gsrc))
#define CP_COMMIT() asm volatile("cp.async.commit_group;" ::: "memory")
#define CP_WAIT1()  asm volatile("cp.async.wait_group 1;" ::: "memory")
#define CP_WAIT0()  asm volatile("cp.async.wait_group 0;" ::: "memory")

#define LDSM_X4(r0, r1, r2, r3, addr) \
    asm volatile("ldmatrix.sync.aligned.m8n8.x4.shared.b16 {%0,%1,%2,%3}, [%4];" \
        : "=r"(r0), "=r"(r1), "=r"(r2), "=r"(r3) : "r"(addr))

#define MMA_TF32(c, a, b0, b1) \
    asm volatile("mma.sync.aligned.m16n8k8.row.col.f32.tf32.tf32.f32 " \
        "{%0,%1,%2,%3}, {%4,%5,%6,%7}, {%8,%9}, {%0,%1,%2,%3};" \
        : "+f"((c)[0]), "+f"((c)[1]), "+f"((c)[2]), "+f"((c)[3]) \
        : "r"((a)[0]), "r"((a)[1]), "r"((a)[2]), "r"((a)[3]), "r"(b0), "r"(b1))

// packed fp32x2 FMA (PTX ISA 8.6, sm_100+ base family)
__device__ __forceinline__ void ffma2(unsigned long long& d, unsigned long long a,
                                      unsigned long long b) {
    asm("fma.rn.f32x2 %0, %1, %2, %0;" : "+l"(d) : "l"(a), "l"(b));
}
__device__ __forceinline__ unsigned long long packf2(float x, float y) {
    unsigned long long r;
    asm("mov.b64 %0, {%1, %2};" : "=l"(r) : "r"(__float_as_uint(x)), "r"(__float_as_uint(y)));
    return r;
}
__device__ __forceinline__ void unpackf2(unsigned long long v, float& x, float& y) {
    uint32_t a, b;
    asm("mov.b64 {%0, %1}, %2;" : "=r"(a), "=r"(b) : "l"(v));
    x = __uint_as_float(a);
    y = __uint_as_float(b);
}

// ---------------- small kernels ---------------------------------------------
__global__ void zero_kernel(float* p, int n) {
    int i = blockIdx.x * 256 + threadIdx.x;
    if (i < n) p[i] = 0.0f;
}

// dst[c][r] = tf32(src[r][c]); src is [R, C] row-major
__global__ void transpose_kernel(const float* __restrict__ src, float* __restrict__ dst,
                                 int R, int C) {
    __shared__ float tile[32][33];
    int c0 = blockIdx.x * 32, r0 = blockIdx.y * 32;
    int tx = threadIdx.x, ty = threadIdx.y;  // (32, 8)
    #pragma unroll
    for (int i = 0; i < 32; i += 8)
        tile[ty + i][tx] = src[(size_t)(r0 + ty + i) * C + c0 + tx];
    __syncthreads();
    #pragma unroll
    for (int i = 0; i < 32; i += 8)
        dst[(size_t)(c0 + ty + i) * R + r0 + tx] = f2tf(tile[tx][ty + i]);
}

__global__ void embed_kernel(const int* __restrict__ ids, const float* __restrict__ E,
                             float* __restrict__ X) {
    int r = blockIdx.x;
    int t = r >> 5;
    int b = r & 31;
    int tok = ids[b * TT + t];
    const float4* src = (const float4*)(E + (size_t)tok * DD);
    float4 v = src[threadIdx.x];
    v.x = f2tf(v.x); v.y = f2tf(v.y); v.z = f2tf(v.z); v.w = f2tf(v.w);
    ((float4*)(X + (size_t)r * DD))[threadIdx.x] = v;
}

// ---------------- tf32 mma.sync GEMM (validated R4) --------------------------
__device__ __forceinline__ void ld_tile(const float* __restrict__ src, size_t row0,
                                        int kc, uint32_t sbase, int tid) {
    #pragma unroll
    for (int i = 0; i < 4; i++) {
        int s = tid + i * 256;
        int r = s >> 3, cs = s & 7;
        const float* g = src + (row0 + r) * DD + kc * BK + cs * 4;
        uint32_t off = (uint32_t)(r * 128 + cs * 16) ^ ((r & 7) << 4);
        CP_ASYNC16(sbase + off, g);
    }
}

__global__ __launch_bounds__(256)
void tf32_gemm_kernel(const float* __restrict__ A, const float* __restrict__ Bt,
                      const float* __restrict__ bias, float* __restrict__ C, int ldc) {
    extern __shared__ char smem_raw[];
    uint32_t raw_u = s2u(smem_raw);
    uint32_t base_u = (raw_u + 1023) & ~1023u;
    uint32_t sa_u[2] = { base_u,          base_u + 2 * TILE_B };
    uint32_t sb_u[2] = { base_u + TILE_B, base_u + 3 * TILE_B };

    int tid = threadIdx.x;
    int lane = tid & 31, wid = tid >> 5;
    int wm = wid & 3, wn = wid >> 2;
    size_t m0 = (size_t)blockIdx.y * BM;
    size_t n0 = (size_t)blockIdx.x * BN;

    int q = lane >> 3;
    int ar = wm * 32 + (q & 1) * 8 + (lane & 7);
    uint32_t apre[2], amask = (uint32_t)((ar & 7) << 4);
    apre[0] = (uint32_t)(ar * 128 + (q >> 1) * 16);
    apre[1] = apre[0] + 16 * 128;
    int br = wn * 64 + (q >> 1) * 8 + (lane & 7);
    uint32_t bpre[4], bmask = (uint32_t)((br & 7) << 4);
    bpre[0] = (uint32_t)(br * 128 + (q & 1) * 16);
    bpre[1] = bpre[0] + 16 * 128;
    bpre[2] = bpre[0] + 32 * 128;
    bpre[3] = bpre[0] + 48 * 128;

    float acc[2][8][4];
    #pragma unroll
    for (int i = 0; i < 2; i++)
        #pragma unroll
        for (int j = 0; j < 8; j++)
            #pragma unroll
            for (int k = 0; k < 4; k++) acc[i][j][k] = 0.0f;

    ld_tile(A,  m0, 0, sa_u[0], tid);
    ld_tile(Bt, n0, 0, sb_u[0], tid);
    CP_COMMIT();

    int buf = 0;
    #pragma unroll 1
    for (int it = 0; it < NCHUNK; it++) {
        if (it + 1 < NCHUNK) {
            ld_tile(A,  m0, it + 1, sa_u[buf ^ 1], tid);
            ld_tile(Bt, n0, it + 1, sb_u[buf ^ 1], tid);
            CP_COMMIT();
            CP_WAIT1();
        } else {
            CP_WAIT0();
        }
        __syncthreads();

        uint32_t As = sa_u[buf], Bs = sb_u[buf];
        #pragma unroll
        for (int ks = 0; ks < 4; ks++) {
            uint32_t a[2][4], b[4][4];
            #pragma unroll
            for (int mt = 0; mt < 2; mt++)
                LDSM_X4(a[mt][0], a[mt][1], a[mt][2], a[mt][3],
                        As + (((apre[mt] + ks * 32) ^ amask)));
            #pragma unroll
            for (int np = 0; np < 4; np++)
                LDSM_X4(b[np][0], b[np][1], b[np][2], b[np][3],
                        Bs + (((bpre[np] + ks * 32) ^ bmask)));
            #pragma unroll
            for (int mt = 0; mt < 2; mt++)
                #pragma unroll
                for (int nt = 0; nt < 8; nt++)
                    MMA_TF32(acc[mt][nt], a[mt], b[nt >> 1][(nt & 1) * 2],
                             b[nt >> 1][(nt & 1) * 2 + 1]);
        }
        __syncthreads();
        buf ^= 1;
    }

    int g = lane >> 2, tg = lane & 3;
    #pragma unroll
    for (int mt = 0; mt < 2; mt++) {
        size_t row = m0 + wm * 32 + mt * 16 + g;
        #pragma unroll
        for (int nt = 0; nt < 8; nt++) {
            size_t col = n0 + wn * 64 + nt * 8 + 2 * tg;
            float b0 = 0.f, b1 = 0.f;
            if (bias) { b0 = bias[col]; b1 = bias[col + 1]; }
            float2 v0 = make_float2(acc[mt][nt][0] + b0, acc[mt][nt][1] + b1);
            float2 v1 = make_float2(acc[mt][nt][2] + b0, acc[mt][nt][3] + b1);
            *(float2*)(C + row * (size_t)ldc + col)       = v0;
            *(float2*)(C + (row + 8) * (size_t)ldc + col) = v1;
        }
    }
}

// ---------------- persistent LSTM v2 -----------------------------------------
// 128 blocks. Weights in registers (k interleaved: thread kq owns k = 4i+kq).
// h stored PACKED as float2 (batch pair, k): hp[b>>1][k].{x,y}. f32x2 FMA.
// c lives in gate-thread registers across all steps; per-bq grid barrier.
__global__ __launch_bounds__(256)
void lstm_persistent2(const float* __restrict__ xz, const float* __restrict__ Wh,
                      const int* __restrict__ len, float* __restrict__ c_glob,
                      float* __restrict__ hp0f, float* __restrict__ hp1f,
                      float* __restrict__ hs, unsigned* __restrict__ bar, int dec) {
    __shared__ unsigned long long hp_s[4 * 512];   // this block's 8 batches, packed
    __shared__ float z_s[64][12];
    int tid = threadIdx.x;
    int w = tid >> 5, l = tid & 31;
    int ux = blockIdx.x & 31, bq = blockIdx.x >> 5;
    int u0 = ux * 16, b0 = bq * 8;
    int jl = w * 8 + (l >> 2);            // 0..63 column of this block
    int kq = l & 3;
    int jg = ((jl >> 4) << 9) + u0 + (jl & 15);

    // weights: thread owns k = 4i + kq, column jg
    float wreg[128];
    #pragma unroll
    for (int i = 0; i < 128; i++)
        wreg[i] = Wh[(size_t)(4 * i + kq) * G4 + jg];

    // gate-thread state (tid < 128)
    int u = tid & 15, bb = tid >> 4;       // unit, local batch
    int b = b0 + bb, uu = u0 + u;
    int myl = 0;
    float cval = 0.0f;
    if (tid < 128) {
        myl = len[b];
        if (dec) cval = c_glob[(size_t)b * HH + uu];
    }

    const unsigned long long* hpg[2] = {
        (const unsigned long long*)hp0f + (size_t)bq * 4 * 512,
        (const unsigned long long*)hp1f + (size_t)bq * 4 * 512 };
    float* hpw[2] = { hp0f, hp1f };
    unsigned target = 0;

    #pragma unroll 1
    for (int t = 0; t < TT; t++) {
        // prefetch xz for gate phase
        float xzv[4];
        if (tid < 128) {
            const float* xp = xz + (size_t)(t * BB + b) * G4 + uu;
            #pragma unroll
            for (int g = 0; g < 4; g++) xzv[g] = xp[g * HH];
        }
        // stage packed h for this block's 8 batches (4 b2 rows)
        {
            const float4* src = (const float4*)hpg[t & 1];
            float4* dst = (float4*)hp_s;
            #pragma unroll
            for (int i = 0; i < 4; i++) dst[tid + i * 256] = src[tid + i * 256];
        }
        __syncthreads();

        // partial dot products over this thread's k set
        unsigned long long acc2[4] = {0ull, 0ull, 0ull, 0ull};
        #pragma unroll
        for (int i = 0; i < 128; i++) {
            unsigned long long wd = packf2(wreg[i], wreg[i]);
            int k = 4 * i + kq;
            ffma2(acc2[0], wd, hp_s[k]);
            ffma2(acc2[1], wd, hp_s[512 + k]);
            ffma2(acc2[2], wd, hp_s[1024 + k]);
            ffma2(acc2[3], wd, hp_s[1536 + k]);
        }
        float s[8];
        #pragma unroll
        for (int b2 = 0; b2 < 4; b2++) unpackf2(acc2[b2], s[2 * b2], s[2 * b2 + 1]);
        #pragma unroll
        for (int j = 0; j < 8; j++) {
            s[j] += __shfl_xor_sync(0xffffffffu, s[j], 1, 4);
            s[j] += __shfl_xor_sync(0xffffffffu, s[j], 2, 4);
        }
        z_s[jl][2 * kq]     = s[2 * kq];
        z_s[jl][2 * kq + 1] = s[2 * kq + 1];
        __syncthreads();

        if (tid < 128) {
            float zi = xzv[0] + z_s[u][bb];
            float zj = xzv[1] + z_s[16 + u][bb];
            float zf = xzv[2] + z_s[32 + u][bb];
            float zo = xzv[3] + z_s[48 + u][bb];
            float* hn_dst = hpw[(t + 1) & 1] + ((size_t)(b >> 1) * 512 + uu) * 2 + (b & 1);
            if (t < myl) {
                cval = cval * sigf(zf + 1.0f) + sigf(zi) * tanhf(zj);
                float hn = tanhf(cval) * sigf(zo);
                *hn_dst = hn;
                if (dec) hs[((size_t)b * TT + t) * HH + uu] = f2tf(hn);
            } else {
                float hprev = ((const float*)hp_s)[((size_t)(bb >> 1) * 512 + uu) * 2 + (b & 1)];
                *hn_dst = hprev;
                if (dec) hs[((size_t)b * TT + t) * HH + uu] = 0.0f;
            }
        }
        __syncthreads();
        // per-bq barrier (32 blocks)
        target += 32;
        if (tid == 0) {
            __threadfence();
            atomicAdd(&bar[bq], 1u);
            unsigned v;
            do {
                asm volatile("ld.acquire.gpu.u32 %0, [%1];" : "=r"(v) : "l"(&bar[bq]));
            } while (v < target);
        }
        __syncthreads();
    }
    // hand off final cell state
    if (tid < 128) c_glob[(size_t)b * HH + uu] = cval;
}

// ---------------- host launch ------------------------------------------------
extern "C" void kernel_launch(void* const* d_in, const int* in_sizes, int n_in,
                              void* d_out, int out_size) {
    const int*   enc_ids = (const int*)d_in[0];
    const int*   dec_ids = (const int*)d_in[1];
    const int*   len_enc = (const int*)d_in[2];
    const int*   len_dec = (const int*)d_in[3];
    const float* E       = (const float*)d_in[4];
    const float* enc_W   = (const float*)d_in[5];
    const float* enc_b   = (const float*)d_in[6];
    const float* dec_W   = (const float*)d_in[7];
    const float* dec_b   = (const float*)d_in[8];
    const float* proj_W  = (const float*)d_in[9];
    float* out = (float*)d_out;

    float *xz_e, *xz_d, *X, *state, *hs, *WtP, *WtE, *WtD;
    cudaGetSymbolAddress((void**)&xz_e,  g_xz_enc);
    cudaGetSymbolAddress((void**)&xz_d,  g_xz_dec);
    cudaGetSymbolAddress((void**)&X,     g_X);
    cudaGetSymbolAddress((void**)&state, g_state);
    cudaGetSymbolAddress((void**)&hs,    g_hs);
    cudaGetSymbolAddress((void**)&WtP,   g_WtP);
    cudaGetSymbolAddress((void**)&WtE,   g_WtE);
    cudaGetSymbolAddress((void**)&WtD,   g_WtD);
    float* c   = state;
    float* hp0 = state + BB * HH;
    float* hp1 = state + 2 * BB * HH;
    unsigned* bars = (unsigned*)(state + 3 * BB * HH);

    cudaFuncSetAttribute(tf32_gemm_kernel,
                         cudaFuncAttributeMaxDynamicSharedMemorySize, GEMM_SMEM);

    // [0] zero c, hp0, hp1, barrier counters
    zero_kernel<<<(3 * BB * HH + 16 + 255) / 256, 256>>>(state, 3 * BB * HH + 16);
    // [1] enc weight transpose, [2] enc embed, [3] enc input GEMM  <- profiled
    transpose_kernel<<<dim3(G4 / 32, DD / 32), dim3(32, 8)>>>(enc_W, WtE, DD, G4);
    embed_kernel<<<MROW, 128>>>(enc_ids, E, X);
    tf32_gemm_kernel<<<dim3(G4 / BN, MROW / BM), 256, GEMM_SMEM>>>(X, WtE, enc_b, xz_e, G4);
    // [4] encoder LSTM (bars 0..3)
    lstm_persistent2<<<NBLK, 256>>>(xz_e, enc_W + (size_t)DD * G4, len_enc,
                                    c, hp0, hp1, nullptr, bars, 0);

    // [5..7] decoder preprocessing
    transpose_kernel<<<dim3(G4 / 32, DD / 32), dim3(32, 8)>>>(dec_W, WtD, DD, G4);
    embed_kernel<<<MROW, 128>>>(dec_ids, E, X);
    tf32_gemm_kernel<<<dim3(G4 / BN, MROW / BM), 256, GEMM_SMEM>>>(X, WtD, dec_b, xz_d, G4);
    // [8] decoder LSTM (bars 4..7)
    lstm_persistent2<<<NBLK, 256>>>(xz_d, dec_W + (size_t)DD * G4, len_dec,
                                    c, hp0, hp1, hs, bars + 4, 1);

    // [9] proj transpose, [10] vocab projection
    transpose_kernel<<<dim3(VV / 32, DD / 32), dim3(32, 8)>>>(proj_W, WtP, DD, VV);
    tf32_gemm_kernel<<<dim3(VV / BN, MROW / BM), 256, GEMM_SMEM>>>(hs, WtP, nullptr, out, VV);
}